// round 8
// baseline (speedup 1.0000x reference)
#include <cuda_runtime.h>
#include <math_constants.h>

#define NPTS 16384
#define KK 10
#define CB 64
#define CTILE 32
#define HALF (NPTS/2)
#define NCHUNK (NPTS/64)

// ---------------- scratch (device globals; no allocation) ----------------
__device__ __align__(16) float d_sq[NPTS];
__device__ int   d_idx[NPTS*KK];
__device__ __align__(16) float d_f1[NPTS*CB];
__device__ __align__(16) float d_f2[NPTS*CB];
__device__ __align__(16) float d_f3[NPTS*CB];
__device__ __align__(16) float d_f4[NPTS*CB];
__device__ __align__(16) float d_Abuf[NPTS*CB];
__device__ __align__(16) float d_Cbuf[NPTS*CB];
__device__ __align__(16) float d_maxh[NPTS*CB];
__device__ __align__(16) float d_minh[NPTS*CB];
__device__ float d_sum[CB];
__device__ float d_ss[CB];
__device__ int   d_ctr;
__device__ int   d_starts[65];
__device__ float d_P[64*256];

// Resolve feature-buffer id -> device pointer IN DEVICE CODE.
// (Passing __device__ symbols as kernel args from host passes the host-side
//  shadow address — on GB300/ATS that silently dereferences host memory.)
__device__ __forceinline__ float* fbuf(int id){
    switch(id){
        case 1: return d_f1;
        case 2: return d_f2;
        case 3: return d_f3;
        default: return d_f4;
    }
}

// ---------------- packed f32x2 helpers ----------------
__device__ __forceinline__ unsigned long long ffma2(unsigned long long a, unsigned long long b, unsigned long long c){
    unsigned long long r;
    asm("fma.rn.f32x2 %0, %1, %2, %3;" : "=l"(r) : "l"(a), "l"(b), "l"(c));
    return r;
}
__device__ __forceinline__ unsigned long long fadd2(unsigned long long a, unsigned long long b){
    unsigned long long r;
    asm("add.rn.f32x2 %0, %1, %2;" : "=l"(r) : "l"(a), "l"(b));
    return r;
}
__device__ __forceinline__ float hsum2(unsigned long long v){
    float lo, hi;
    asm("mov.b64 {%0,%1}, %2;" : "=f"(lo), "=f"(hi) : "l"(v));
    return lo + hi;
}

// ---------------- squared norms ----------------
__global__ void sq3_kernel(const float* __restrict__ x){
    int i = blockIdx.x*blockDim.x + threadIdx.x;
    if (i >= NPTS) return;
    float a = x[i*3], b = x[i*3+1], c = x[i*3+2];
    d_sq[i] = a*a + b*b + c*c;
}

__global__ void sq64_kernel(int id){
    const float* x = fbuf(id);
    int i = blockIdx.x*blockDim.x + threadIdx.x;
    if (i >= NPTS) return;
    float s = 0.f;
    const float4* p = (const float4*)(x + (long)i*CB);
    #pragma unroll
    for (int q = 0; q < CB/4; q++){ float4 v = p[q]; s += v.x*v.x + v.y*v.y + v.z*v.z + v.w*v.w; }
    d_sq[i] = s;
}

// ---------------- kNN for 3-dim coords ----------------
__global__ __launch_bounds__(128) void knn3_kernel(const float* __restrict__ x){
    __shared__ float4 sc[256];
    int i = blockIdx.x*128 + threadIdx.x;
    float xi = x[i*3], yi = x[i*3+1], zi = x[i*3+2], sqi = d_sq[i];
    float bd[KK]; int bi[KK];
    #pragma unroll
    for (int q = 0; q < KK; q++){ bd[q] = CUDART_INF_F; bi[q] = 0x7fffffff; }
    for (int base = 0; base < NPTS; base += 256){
        __syncthreads();
        for (int v = threadIdx.x; v < 256; v += 128){
            int c = base + v;
            sc[v] = make_float4(x[c*3], x[c*3+1], x[c*3+2], d_sq[c]);
        }
        __syncthreads();
        #pragma unroll 4
        for (int j = 0; j < 256; j++){
            float4 cv = sc[j];
            float dist = sqi + cv.w - 2.f*(xi*cv.x + yi*cv.y + zi*cv.z);
            if (dist < bd[KK-1]){
                float cd = dist; int ci = base + j;
                #pragma unroll
                for (int q = 0; q < KK; q++){
                    if (cd < bd[q]){ float td = bd[q]; int ti = bi[q]; bd[q] = cd; bi[q] = ci; cd = td; ci = ti; }
                }
            }
        }
    }
    #pragma unroll
    for (int q = 0; q < KK; q++) d_idx[i*KK+q] = bi[q];
}

// ---------------- kNN for 64-dim features (persistent, packed f32x2) ----------------
__global__ __launch_bounds__(128, 4) void knn64_kernel(int id){
    const float* f = fbuf(id);
    __shared__ __align__(16) float scol[2][CTILE*64];
    __shared__ float ssq[2][CTILE];
    __shared__ float mdq[64][2*KK];
    __shared__ int   miq[64][2*KK];
    __shared__ int   s_chunk;
    const int t = threadIdx.x;
    const int split = t >> 6;        // 0..1 column half
    const int rl = t & 63;           // row within chunk
    while (true){
        __syncthreads();
        if (t == 0) s_chunk = atomicAdd(&d_ctr, 1);
        __syncthreads();
        int chunk = s_chunk;
        if (chunk >= NCHUNK) return; // uniform exit
        int row = chunk*64 + rl;
        unsigned long long rp[32];
        {
            const ulonglong2* rr = (const ulonglong2*)(f + (long)row*64);
            #pragma unroll
            for (int q = 0; q < 16; q++){ ulonglong2 v = rr[q]; rp[2*q] = v.x; rp[2*q+1] = v.y; }
        }
        float sqi = d_sq[row];
        float bd[KK]; int bi[KK];
        #pragma unroll
        for (int q = 0; q < KK; q++){ bd[q] = CUDART_INF_F; bi[q] = 0x7fffffff; }

        for (int tile = 0; tile < HALF; tile += CTILE){
            __syncthreads();
            // cooperative load of both splits' 32-col tiles (4096 floats)
            #pragma unroll
            for (int v = t; v < 2*CTILE*16; v += 128){
                int colr = v >> 4;            // 0..63
                int q    = v & 15;
                int sp   = colr >> 5;
                int cc   = colr & 31;
                int gcol = sp*HALF + tile + cc;
                ((float4*)scol)[v] = ((const float4*)(f + (long)gcol*64))[q];
            }
            if (t < 2*CTILE){
                int sp = t >> 5, cc = t & 31;
                ssq[sp][cc] = d_sq[sp*HALF + tile + cc];
            }
            __syncthreads();
            const float* mc = scol[split];
            int cbase = split*HALF + tile;
            #pragma unroll 2
            for (int j = 0; j < CTILE; j++){
                const ulonglong2* cp = (const ulonglong2*)(mc + j*64);
                unsigned long long a0 = 0ull, a1 = 0ull, a2 = 0ull, a3 = 0ull;
                #pragma unroll
                for (int q = 0; q < 16; q += 2){
                    ulonglong2 c0 = cp[q];
                    ulonglong2 c1 = cp[q+1];
                    a0 = ffma2(rp[2*q],   c0.x, a0);
                    a1 = ffma2(rp[2*q+1], c0.y, a1);
                    a2 = ffma2(rp[2*q+2], c1.x, a2);
                    a3 = ffma2(rp[2*q+3], c1.y, a3);
                }
                a0 = fadd2(a0, a1); a2 = fadd2(a2, a3); a0 = fadd2(a0, a2);
                float dot  = hsum2(a0);
                float dist = sqi + ssq[split][j] - 2.f*dot;
                if (dist < bd[KK-1]){
                    float cd = dist; int ci = cbase + j;
                    #pragma unroll
                    for (int q = 0; q < KK; q++){
                        if (cd < bd[q]){ float td = bd[q]; int ti = bi[q]; bd[q] = cd; bi[q] = ci; cd = td; ci = ti; }
                    }
                }
            }
        }
        // merge the two column-half top-10 lists, (dist, idx) lexicographic
        #pragma unroll
        for (int q = 0; q < KK; q++){ mdq[rl][split*KK+q] = bd[q]; miq[rl][split*KK+q] = bi[q]; }
        __syncthreads();
        if (split == 0){
            int pa = 0, pb = KK;
            #pragma unroll
            for (int q = 0; q < KK; q++){
                int par = min(pa, 2*KK-1), pbr = min(pb, 2*KK-1);
                float da = mdq[rl][par]; int ia = miq[rl][par];
                float db = mdq[rl][pbr]; int ib = miq[rl][pbr];
                bool takeA;
                if (pb >= 2*KK) takeA = true;
                else if (pa >= KK) takeA = false;
                else takeA = (da < db) || (da == db && ia < ib);
                d_idx[row*KK+q] = takeA ? ia : ib;
                if (takeA) pa++; else pb++;
            }
        }
    }
}

// ---------------- per-point projections: a = x@(Wt-Wb), c = x@Wb ----------------
__global__ void proj3_kernel(const float* __restrict__ x, const float* __restrict__ W){
    __shared__ float sWa[3*64];
    __shared__ float sWb[3*64];
    for (int v = threadIdx.x; v < 3*64; v += 256){
        float wb = W[3*64 + v];
        sWa[v] = W[v] - wb;
        sWb[v] = wb;
    }
    __syncthreads();
    int o  = threadIdx.x & 63;
    int rg = threadIdx.x >> 6;
    int row0 = blockIdx.x * 64;
    for (int rr = 0; rr < 64; rr += 4){
        int row = row0 + rr + rg;
        float av = 0.f, cv = 0.f;
        #pragma unroll
        for (int d = 0; d < 3; d++){
            float xv = __ldg(x + (long)row*3 + d);
            av += xv * sWa[d*64+o];
            cv += xv * sWb[d*64+o];
        }
        d_Abuf[row*64+o] = av; d_Cbuf[row*64+o] = cv;
    }
}

__global__ void proj64_kernel(int id, const float* __restrict__ W){
    const float* x = fbuf(id);
    __shared__ float sWa[64*64];
    __shared__ float sWb[64*64];
    for (int v = threadIdx.x; v < 64*64; v += 256){
        float wb = W[64*64 + v];
        sWa[v] = W[v] - wb;
        sWb[v] = wb;
    }
    __syncthreads();
    int o  = threadIdx.x & 63;
    int rg = threadIdx.x >> 6;
    int row0 = blockIdx.x * 64;
    for (int rr = 0; rr < 64; rr += 4){
        int row = row0 + rr + rg;
        float av = 0.f, cv = 0.f;
        #pragma unroll
        for (int d = 0; d < 64; d++){
            float xv = __ldg(x + (long)row*64 + d);
            av += xv * sWa[d*64+o];
            cv += xv * sWb[d*64+o];
        }
        d_Abuf[row*64+o] = av; d_Cbuf[row*64+o] = cv;
    }
}

// ---------------- gather + pool (BN layers: stats + max/min) ----------------
__global__ void pool_bn_kernel(const float* __restrict__ bias){
    int o  = threadIdx.x & 63;
    int rg = threadIdx.x >> 6;
    int row = blockIdx.x*4 + rg;
    float a = d_Abuf[row*64+o] + bias[o];
    float mx = -CUDART_INF_F, mn = CUDART_INF_F, s = 0.f, s2 = 0.f;
    #pragma unroll
    for (int k = 0; k < KK; k++){
        int j = d_idx[row*KK+k];
        float h = a + d_Cbuf[j*64+o];
        mx = fmaxf(mx, h); mn = fminf(mn, h);
        s += h; s2 += h*h;
    }
    d_maxh[row*64+o] = mx; d_minh[row*64+o] = mn;
    __shared__ float reds[4][64], reds2[4][64];
    reds[rg][o] = s; reds2[rg][o] = s2;
    __syncthreads();
    if (rg == 0){
        float ts = reds[0][o]+reds[1][o]+reds[2][o]+reds[3][o];
        float t2 = reds2[0][o]+reds2[1][o]+reds2[2][o]+reds2[3][o];
        atomicAdd(&d_sum[o], ts);
        atomicAdd(&d_ss[o],  t2);
    }
}

__global__ void bn_apply_kernel(const float* __restrict__ gamma, const float* __restrict__ beta,
                                int outid){
    float* out = fbuf(outid);
    int gid = blockIdx.x*blockDim.x + threadIdx.x;
    int o = gid & 63;
    const float inv = 1.f/(float)(NPTS*KK);
    float mu  = d_sum[o]*inv;
    float var = d_ss[o]*inv - mu*mu;
    float g = gamma[o];
    float s = rsqrtf(var + 1e-5f) * g;
    float pool = (g >= 0.f) ? d_maxh[gid] : d_minh[gid];
    float v = pool*s + (beta[o] - mu*s);
    out[gid] = fmaxf(v, 0.f);
}

// ---------------- gather + pool (plain layers) ----------------
__global__ void pool_plain_kernel(const float* __restrict__ bias, int outid){
    float* out = fbuf(outid);
    int gid = blockIdx.x*blockDim.x + threadIdx.x;
    int o = gid & 63; int row = gid >> 6;
    float cmax = -CUDART_INF_F;
    #pragma unroll
    for (int k = 0; k < KK; k++){
        int j = d_idx[row*KK+k];
        cmax = fmaxf(cmax, d_Cbuf[j*64+o]);
    }
    out[gid] = fmaxf(d_Abuf[gid] + bias[o] + cmax, 0.f);
}

// ---------------- misc ----------------
__global__ void reset_kernel(){
    if (threadIdx.x == 0) d_ctr = 0;
    if (threadIdx.x < 64){ d_sum[threadIdx.x] = 0.f; d_ss[threadIdx.x] = 0.f; }
}

__global__ void starts_kernel(const int* __restrict__ n_pts){
    if (threadIdx.x == 0){
        int acc = 0;
        for (int b = 0; b < 64; b++){ d_starts[b] = acc; acc += n_pts[b]; }
        d_starts[64] = acc;
    }
}

__global__ void agg_kernel(){
    int b = blockIdx.x;
    int l = threadIdx.x >> 6, o = threadIdx.x & 63;
    const float* f = (l == 0) ? d_f1 : (l == 1) ? d_f2 : (l == 2) ? d_f3 : d_f4;
    int s = min(d_starts[b], NPTS);
    int e = (b == 63) ? NPTS : min(d_starts[b+1], NPTS);
    float m = -CUDART_INF_F;
    for (int p = s; p < e; p++) m = fmaxf(m, f[p*64+o]);
    d_P[b*256 + l*64 + o] = m;
}

__global__ void final_kernel(const float* __restrict__ Wp, const float* __restrict__ bp,
                             float* __restrict__ out){
    int b = blockIdx.x; int o = threadIdx.x;  // 128 threads
    __shared__ float sp[256];
    for (int v = o; v < 256; v += 128) sp[v] = d_P[b*256+v];
    __syncthreads();
    float acc = bp[o];
    #pragma unroll 4
    for (int d = 0; d < 256; d++) acc += sp[d]*Wp[d*128+o];
    float v = tanhf(acc);
    float sq = v*v;
    #pragma unroll
    for (int off = 16; off > 0; off >>= 1) sq += __shfl_xor_sync(0xffffffffu, sq, off);
    __shared__ float rs[4];
    if ((o & 31) == 0) rs[o>>5] = sq;
    __syncthreads();
    float tot = rs[0]+rs[1]+rs[2]+rs[3];
    out[b*128+o] = v / (sqrtf(tot) + 1e-9f);
}

// ---------------- launch ----------------
extern "C" void kernel_launch(void* const* d_in, const int* in_sizes, int n_in,
                              void* d_out, int out_size){
    (void)in_sizes; (void)n_in; (void)out_size;
    const float* x     = (const float*)d_in[0];
    const int*   n_pts = (const int*)  d_in[1];
    const float* W1 = (const float*)d_in[2];  const float* b1  = (const float*)d_in[3];
    const float* g1 = (const float*)d_in[4];  const float* be1 = (const float*)d_in[5];
    const float* W2 = (const float*)d_in[6];  const float* b2  = (const float*)d_in[7];
    const float* W3 = (const float*)d_in[8];  const float* b3  = (const float*)d_in[9];
    const float* g3 = (const float*)d_in[10]; const float* be3 = (const float*)d_in[11];
    const float* W4 = (const float*)d_in[12]; const float* b4  = (const float*)d_in[13];
    const float* Wp = (const float*)d_in[14]; const float* bp  = (const float*)d_in[15];
    float* out = (float*)d_out;

    // ---- layer 1 (C=3, BN) ----
    sq3_kernel<<<NPTS/256, 256>>>(x);
    knn3_kernel<<<128, 128>>>(x);
    proj3_kernel<<<NPTS/64, 256>>>(x, W1);
    reset_kernel<<<1, 64>>>();
    pool_bn_kernel<<<NPTS/4, 256>>>(b1);
    bn_apply_kernel<<<NPTS*64/256, 256>>>(g1, be1, 1);

    // ---- layer 2 (C=64, no BN) ----
    sq64_kernel<<<NPTS/256, 256>>>(1);
    reset_kernel<<<1, 64>>>();
    knn64_kernel<<<592, 128>>>(1);
    proj64_kernel<<<NPTS/64, 256>>>(1, W2);
    pool_plain_kernel<<<NPTS*64/256, 256>>>(b2, 2);

    // ---- layer 3 (C=64, BN) ----
    sq64_kernel<<<NPTS/256, 256>>>(2);
    reset_kernel<<<1, 64>>>();
    knn64_kernel<<<592, 128>>>(2);
    proj64_kernel<<<NPTS/64, 256>>>(2, W3);
    pool_bn_kernel<<<NPTS/4, 256>>>(b3);
    bn_apply_kernel<<<NPTS*64/256, 256>>>(g3, be3, 3);

    // ---- layer 4 (C=64, no BN) ----
    sq64_kernel<<<NPTS/256, 256>>>(3);
    reset_kernel<<<1, 64>>>();
    knn64_kernel<<<592, 128>>>(3);
    proj64_kernel<<<NPTS/64, 256>>>(3, W4);
    pool_plain_kernel<<<NPTS*64/256, 256>>>(b4, 4);

    // ---- head ----
    starts_kernel<<<1, 32>>>(n_pts);
    agg_kernel<<<64, 256>>>();
    final_kernel<<<64, 128>>>(Wp, bp, out);
}

// round 9
// speedup vs baseline: 1.0567x; 1.0567x over previous
#include <cuda_runtime.h>
#include <math_constants.h>

#define NPTS 16384
#define KK 10
#define CB 64
#define PAD 68
#define BR 32
#define BC 64
#define NT (NPTS/BC)     /* 256 col tiles per sweep */
#define NCH (NPTS/BR)    /* 512 row chunks */

// ---------------- scratch (device globals; no allocation) ----------------
__device__ __align__(16) float d_sq[NPTS];
__device__ int   d_idx[NPTS*KK];
__device__ __align__(16) float d_f1[NPTS*CB];
__device__ __align__(16) float d_f2[NPTS*CB];
__device__ __align__(16) float d_f3[NPTS*CB];
__device__ __align__(16) float d_f4[NPTS*CB];
__device__ __align__(16) float d_Abuf[NPTS*CB];
__device__ __align__(16) float d_Cbuf[NPTS*CB];
__device__ __align__(16) float d_maxh[NPTS*CB];
__device__ __align__(16) float d_minh[NPTS*CB];
__device__ float d_sum[CB];
__device__ float d_ss[CB];
__device__ int   d_ctr;
__device__ int   d_starts[65];
__device__ float d_P[64*256];

// Resolve feature-buffer id -> device pointer IN DEVICE CODE (host-side
// __device__ symbol decay passes the host shadow address under ATS).
__device__ __forceinline__ float* fbuf(int id){
    switch(id){
        case 1: return d_f1;
        case 2: return d_f2;
        case 3: return d_f3;
        default: return d_f4;
    }
}

// ---------------- packed f32x2 helpers ----------------
__device__ __forceinline__ unsigned long long ffma2(unsigned long long a, unsigned long long b, unsigned long long c){
    unsigned long long r;
    asm("fma.rn.f32x2 %0, %1, %2, %3;" : "=l"(r) : "l"(a), "l"(b), "l"(c));
    return r;
}
__device__ __forceinline__ float hsum2(unsigned long long v){
    float lo, hi;
    asm("mov.b64 {%0,%1}, %2;" : "=f"(lo), "=f"(hi) : "l"(v));
    return lo + hi;
}

// ---------------- cp.async helpers ----------------
__device__ __forceinline__ unsigned smaddr(const void* p){
    return (unsigned)__cvta_generic_to_shared(p);
}
__device__ __forceinline__ void cp16(unsigned s, const void* g){
    asm volatile("cp.async.cg.shared.global [%0], [%1], 16;" :: "r"(s), "l"(g));
}
__device__ __forceinline__ void cp4(unsigned s, const void* g){
    asm volatile("cp.async.ca.shared.global [%0], [%1], 4;" :: "r"(s), "l"(g));
}
__device__ __forceinline__ void cp_commit(){ asm volatile("cp.async.commit_group;"); }
__device__ __forceinline__ void cp_wait1(){ asm volatile("cp.async.wait_group 1;"); }
__device__ __forceinline__ void cp_wait0(){ asm volatile("cp.async.wait_group 0;"); }

// ---------------- squared norms ----------------
__global__ void sq3_kernel(const float* __restrict__ x){
    int i = blockIdx.x*blockDim.x + threadIdx.x;
    if (i >= NPTS) return;
    float a = x[i*3], b = x[i*3+1], c = x[i*3+2];
    d_sq[i] = a*a + b*b + c*c;
}

__global__ void sq64_kernel(int id){
    const float* x = fbuf(id);
    int i = blockIdx.x*blockDim.x + threadIdx.x;
    if (i >= NPTS) return;
    float s = 0.f;
    const float4* p = (const float4*)(x + (long)i*CB);
    #pragma unroll
    for (int q = 0; q < CB/4; q++){ float4 v = p[q]; s += v.x*v.x + v.y*v.y + v.z*v.z + v.w*v.w; }
    d_sq[i] = s;
}

// ---------------- kNN for 3-dim coords ----------------
__global__ __launch_bounds__(128) void knn3_kernel(const float* __restrict__ x){
    __shared__ float4 sc[256];
    int i = blockIdx.x*128 + threadIdx.x;
    float xi = x[i*3], yi = x[i*3+1], zi = x[i*3+2], sqi = d_sq[i];
    float bd[KK]; int bi[KK];
    #pragma unroll
    for (int q = 0; q < KK; q++){ bd[q] = CUDART_INF_F; bi[q] = 0x7fffffff; }
    for (int base = 0; base < NPTS; base += 256){
        __syncthreads();
        for (int v = threadIdx.x; v < 256; v += 128){
            int c = base + v;
            sc[v] = make_float4(x[c*3], x[c*3+1], x[c*3+2], d_sq[c]);
        }
        __syncthreads();
        #pragma unroll 4
        for (int j = 0; j < 256; j++){
            float4 cv = sc[j];
            float dist = sqi + cv.w - 2.f*(xi*cv.x + yi*cv.y + zi*cv.z);
            if (dist < bd[KK-1]){
                float cd = dist; int ci = base + j;
                #pragma unroll
                for (int q = 0; q < KK; q++){
                    if (cd < bd[q]){ float td = bd[q]; int ti = bi[q]; bd[q] = cd; bi[q] = ci; cd = td; ci = ti; }
                }
            }
        }
    }
    #pragma unroll
    for (int q = 0; q < KK; q++) d_idx[i*KK+q] = bi[q];
}

// ---------------- kNN for 64-dim features: register-blocked distance GEMM ----
// Block = 256 threads = 32 row_pos x 8 col_pos. Thread: 1 row x 8 cols.
// Per k-quad: 1 row LDS.128 + 8 col LDS.128 -> 16 FFMA2 (fma-pipe-bound).
// Padded SMEM (stride 68 floats) => conflict-free. cp.async double buffer.
__global__ __launch_bounds__(256, 2) void knn64_kernel(int id){
    const float* f = fbuf(id);
    __shared__ union {
        struct { float srow[BR*PAD]; float scol[2][BC*PAD]; float ssq[2][BC]; } k;
        struct { float md[BR*8*KK]; int mi[BR*8*KK]; } m;
    } su;
    __shared__ int s_chunk;
    const int t = threadIdx.x;
    const int row_pos = t >> 3;   // 0..31
    const int col_pos = t & 7;    // 0..7
    const unsigned srow_u = smaddr(su.k.srow);
    const unsigned scol_u = smaddr(su.k.scol);
    const unsigned ssq_u  = smaddr(su.k.ssq);

    while (true){
        __syncthreads();
        if (t == 0) s_chunk = atomicAdd(&d_ctr, 1);
        __syncthreads();
        const int chunk = s_chunk;
        if (chunk >= NCH) return;            // uniform exit
        const int rbase = chunk*BR;

        // preload: row tile (32x64) + col tile 0 (64x64) + ssq tile 0
        #pragma unroll
        for (int i = 0; i < 2; i++){
            int v = t + i*256; int r = v >> 4, q = v & 15;
            cp16(srow_u + (unsigned)(r*PAD + q*4)*4u, f + (size_t)(rbase + r)*64 + q*4);
        }
        #pragma unroll
        for (int i = 0; i < 4; i++){
            int v = t + i*256; int c = v >> 4, q = v & 15;
            cp16(scol_u + (unsigned)(c*PAD + q*4)*4u, f + (size_t)c*64 + q*4);
        }
        if (t < BC) cp4(ssq_u + (unsigned)t*4u, d_sq + t);
        cp_commit();

        const float sqr = d_sq[rbase + row_pos];
        float bd[KK]; int bi[KK];
        #pragma unroll
        for (int q = 0; q < KK; q++){ bd[q] = CUDART_INF_F; bi[q] = 0x7fffffff; }

        for (int tile = 0; tile < NT; tile++){
            const int buf = tile & 1;
            if (tile + 1 < NT){
                const int nb = buf ^ 1;
                const int cb0 = (tile + 1)*BC;
                const unsigned sc_nb = scol_u + (unsigned)(nb*BC*PAD)*4u;
                #pragma unroll
                for (int i = 0; i < 4; i++){
                    int v = t + i*256; int c = v >> 4, q = v & 15;
                    cp16(sc_nb + (unsigned)(c*PAD + q*4)*4u, f + (size_t)(cb0 + c)*64 + q*4);
                }
                if (t < BC) cp4(ssq_u + (unsigned)(nb*BC + t)*4u, d_sq + cb0 + t);
                cp_commit();
                cp_wait1();
            } else {
                cp_wait0();
            }
            __syncthreads();

            // ---- GEMM micro-tile: 1 row x 8 cols over k=64 (16 k-quads) ----
            const float* cb = su.k.scol[buf];
            const float* rowp = su.k.srow + row_pos*PAD;
            unsigned long long acc[8];
            #pragma unroll
            for (int j = 0; j < 8; j++) acc[j] = 0ull;
            #pragma unroll
            for (int kq = 0; kq < 16; kq++){
                ulonglong2 rf = *(const ulonglong2*)(rowp + kq*4);
                #pragma unroll
                for (int j = 0; j < 8; j++){
                    ulonglong2 cf = *(const ulonglong2*)(cb + (col_pos + 8*j)*PAD + kq*4);
                    acc[j] = ffma2(rf.x, cf.x, acc[j]);
                    acc[j] = ffma2(rf.y, cf.y, acc[j]);
                }
            }
            // ---- epilogue: form distances, streaming top-10 insert ----
            #pragma unroll
            for (int j = 0; j < 8; j++){
                int cc = col_pos + 8*j;
                float dist = fmaf(-2.f, hsum2(acc[j]), sqr + su.k.ssq[buf][cc]);
                if (dist < bd[KK-1]){
                    float cd = dist; int ci = tile*BC + cc;
                    #pragma unroll
                    for (int q = 0; q < KK; q++){
                        if (cd < bd[q]){ float td = bd[q]; int ti = bi[q]; bd[q] = cd; bi[q] = ci; cd = td; ci = ti; }
                    }
                }
            }
            __syncthreads();   // protect buf^1 before next iteration's cp.async
        }

        // ---- merge the 8 per-thread lists per row (lexicographic (dist,idx)) ----
        #pragma unroll
        for (int q = 0; q < KK; q++){
            su.m.md[(row_pos*8 + col_pos)*KK + q] = bd[q];
            su.m.mi[(row_pos*8 + col_pos)*KK + q] = bi[q];
        }
        __syncthreads();
        if (t < BR){
            float fd[KK]; int fi[KK];
            #pragma unroll
            for (int q = 0; q < KK; q++){ fd[q] = CUDART_INF_F; fi[q] = 0x7fffffff; }
            for (int s = 0; s < 8*KK; s++){
                float dv = su.m.md[t*8*KK + s];
                int   iv = su.m.mi[t*8*KK + s];
                if (dv < fd[KK-1] || (dv == fd[KK-1] && iv < fi[KK-1])){
                    float cd = dv; int ci = iv;
                    #pragma unroll
                    for (int q = 0; q < KK; q++){
                        if (cd < fd[q] || (cd == fd[q] && ci < fi[q])){
                            float td = fd[q]; int ti = fi[q]; fd[q] = cd; fi[q] = ci; cd = td; ci = ti;
                        }
                    }
                }
            }
            #pragma unroll
            for (int q = 0; q < KK; q++) d_idx[(rbase + t)*KK + q] = fi[q];
        }
        // loop-top __syncthreads() orders merge writes vs next chunk's cp.async
    }
}

// ---------------- per-point projections: a = x@(Wt-Wb), c = x@Wb ----------------
__global__ void proj3_kernel(const float* __restrict__ x, const float* __restrict__ W){
    __shared__ float sWa[3*64];
    __shared__ float sWb[3*64];
    for (int v = threadIdx.x; v < 3*64; v += 256){
        float wb = W[3*64 + v];
        sWa[v] = W[v] - wb;
        sWb[v] = wb;
    }
    __syncthreads();
    int o  = threadIdx.x & 63;
    int rg = threadIdx.x >> 6;
    int row0 = blockIdx.x * 64;
    for (int rr = 0; rr < 64; rr += 4){
        int row = row0 + rr + rg;
        float av = 0.f, cv = 0.f;
        #pragma unroll
        for (int d = 0; d < 3; d++){
            float xv = __ldg(x + (long)row*3 + d);
            av += xv * sWa[d*64+o];
            cv += xv * sWb[d*64+o];
        }
        d_Abuf[row*64+o] = av; d_Cbuf[row*64+o] = cv;
    }
}

__global__ void proj64_kernel(int id, const float* __restrict__ W){
    const float* x = fbuf(id);
    __shared__ float sWa[64*64];
    __shared__ float sWb[64*64];
    for (int v = threadIdx.x; v < 64*64; v += 256){
        float wb = W[64*64 + v];
        sWa[v] = W[v] - wb;
        sWb[v] = wb;
    }
    __syncthreads();
    int o  = threadIdx.x & 63;
    int rg = threadIdx.x >> 6;
    int row0 = blockIdx.x * 64;
    for (int rr = 0; rr < 64; rr += 4){
        int row = row0 + rr + rg;
        float av = 0.f, cv = 0.f;
        #pragma unroll
        for (int d = 0; d < 64; d++){
            float xv = __ldg(x + (long)row*64 + d);
            av += xv * sWa[d*64+o];
            cv += xv * sWb[d*64+o];
        }
        d_Abuf[row*64+o] = av; d_Cbuf[row*64+o] = cv;
    }
}

// ---------------- gather + pool (BN layers: stats + max/min) ----------------
__global__ void pool_bn_kernel(const float* __restrict__ bias){
    int o  = threadIdx.x & 63;
    int rg = threadIdx.x >> 6;
    int row = blockIdx.x*4 + rg;
    float a = d_Abuf[row*64+o] + bias[o];
    float mx = -CUDART_INF_F, mn = CUDART_INF_F, s = 0.f, s2 = 0.f;
    #pragma unroll
    for (int k = 0; k < KK; k++){
        int j = d_idx[row*KK+k];
        float h = a + d_Cbuf[j*64+o];
        mx = fmaxf(mx, h); mn = fminf(mn, h);
        s += h; s2 += h*h;
    }
    d_maxh[row*64+o] = mx; d_minh[row*64+o] = mn;
    __shared__ float reds[4][64], reds2[4][64];
    reds[rg][o] = s; reds2[rg][o] = s2;
    __syncthreads();
    if (rg == 0){
        float ts = reds[0][o]+reds[1][o]+reds[2][o]+reds[3][o];
        float t2 = reds2[0][o]+reds2[1][o]+reds2[2][o]+reds2[3][o];
        atomicAdd(&d_sum[o], ts);
        atomicAdd(&d_ss[o],  t2);
    }
}

__global__ void bn_apply_kernel(const float* __restrict__ gamma, const float* __restrict__ beta,
                                int outid){
    float* out = fbuf(outid);
    int gid = blockIdx.x*blockDim.x + threadIdx.x;
    int o = gid & 63;
    const float inv = 1.f/(float)(NPTS*KK);
    float mu  = d_sum[o]*inv;
    float var = d_ss[o]*inv - mu*mu;
    float g = gamma[o];
    float s = rsqrtf(var + 1e-5f) * g;
    float pool = (g >= 0.f) ? d_maxh[gid] : d_minh[gid];
    float v = pool*s + (beta[o] - mu*s);
    out[gid] = fmaxf(v, 0.f);
}

// ---------------- gather + pool (plain layers) ----------------
__global__ void pool_plain_kernel(const float* __restrict__ bias, int outid){
    float* out = fbuf(outid);
    int gid = blockIdx.x*blockDim.x + threadIdx.x;
    int o = gid & 63; int row = gid >> 6;
    float cmax = -CUDART_INF_F;
    #pragma unroll
    for (int k = 0; k < KK; k++){
        int j = d_idx[row*KK+k];
        cmax = fmaxf(cmax, d_Cbuf[j*64+o]);
    }
    out[gid] = fmaxf(d_Abuf[gid] + bias[o] + cmax, 0.f);
}

// ---------------- misc ----------------
__global__ void reset_kernel(){
    if (threadIdx.x == 0) d_ctr = 0;
    if (threadIdx.x < 64){ d_sum[threadIdx.x] = 0.f; d_ss[threadIdx.x] = 0.f; }
}

__global__ void starts_kernel(const int* __restrict__ n_pts){
    if (threadIdx.x == 0){
        int acc = 0;
        for (int b = 0; b < 64; b++){ d_starts[b] = acc; acc += n_pts[b]; }
        d_starts[64] = acc;
    }
}

__global__ void agg_kernel(){
    int b = blockIdx.x;
    int l = threadIdx.x >> 6, o = threadIdx.x & 63;
    const float* f = (l == 0) ? d_f1 : (l == 1) ? d_f2 : (l == 2) ? d_f3 : d_f4;
    int s = min(d_starts[b], NPTS);
    int e = (b == 63) ? NPTS : min(d_starts[b+1], NPTS);
    float m = -CUDART_INF_F;
    for (int p = s; p < e; p++) m = fmaxf(m, f[p*64+o]);
    d_P[b*256 + l*64 + o] = m;
}

__global__ void final_kernel(const float* __restrict__ Wp, const float* __restrict__ bp,
                             float* __restrict__ out){
    int b = blockIdx.x; int o = threadIdx.x;  // 128 threads
    __shared__ float sp[256];
    for (int v = o; v < 256; v += 128) sp[v] = d_P[b*256+v];
    __syncthreads();
    float acc = bp[o];
    #pragma unroll 4
    for (int d = 0; d < 256; d++) acc += sp[d]*Wp[d*128+o];
    float v = tanhf(acc);
    float sq = v*v;
    #pragma unroll
    for (int off = 16; off > 0; off >>= 1) sq += __shfl_xor_sync(0xffffffffu, sq, off);
    __shared__ float rs[4];
    if ((o & 31) == 0) rs[o>>5] = sq;
    __syncthreads();
    float tot = rs[0]+rs[1]+rs[2]+rs[3];
    out[b*128+o] = v / (sqrtf(tot) + 1e-9f);
}

// ---------------- launch ----------------
extern "C" void kernel_launch(void* const* d_in, const int* in_sizes, int n_in,
                              void* d_out, int out_size){
    (void)in_sizes; (void)n_in; (void)out_size;
    const float* x     = (const float*)d_in[0];
    const int*   n_pts = (const int*)  d_in[1];
    const float* W1 = (const float*)d_in[2];  const float* b1  = (const float*)d_in[3];
    const float* g1 = (const float*)d_in[4];  const float* be1 = (const float*)d_in[5];
    const float* W2 = (const float*)d_in[6];  const float* b2  = (const float*)d_in[7];
    const float* W3 = (const float*)d_in[8];  const float* b3  = (const float*)d_in[9];
    const float* g3 = (const float*)d_in[10]; const float* be3 = (const float*)d_in[11];
    const float* W4 = (const float*)d_in[12]; const float* b4  = (const float*)d_in[13];
    const float* Wp = (const float*)d_in[14]; const float* bp  = (const float*)d_in[15];
    float* out = (float*)d_out;

    // ---- layer 1 (C=3, BN) ----
    sq3_kernel<<<NPTS/256, 256>>>(x);
    knn3_kernel<<<128, 128>>>(x);
    proj3_kernel<<<NPTS/64, 256>>>(x, W1);
    reset_kernel<<<1, 64>>>();
    pool_bn_kernel<<<NPTS/4, 256>>>(b1);
    bn_apply_kernel<<<NPTS*64/256, 256>>>(g1, be1, 1);

    // ---- layer 2 (C=64, no BN) ----
    sq64_kernel<<<NPTS/256, 256>>>(1);
    reset_kernel<<<1, 64>>>();
    knn64_kernel<<<296, 256>>>(1);
    proj64_kernel<<<NPTS/64, 256>>>(1, W2);
    pool_plain_kernel<<<NPTS*64/256, 256>>>(b2, 2);

    // ---- layer 3 (C=64, BN) ----
    sq64_kernel<<<NPTS/256, 256>>>(2);
    reset_kernel<<<1, 64>>>();
    knn64_kernel<<<296, 256>>>(2);
    proj64_kernel<<<NPTS/64, 256>>>(2, W3);
    pool_bn_kernel<<<NPTS/4, 256>>>(b3);
    bn_apply_kernel<<<NPTS*64/256, 256>>>(g3, be3, 3);

    // ---- layer 4 (C=64, no BN) ----
    sq64_kernel<<<NPTS/256, 256>>>(3);
    reset_kernel<<<1, 64>>>();
    knn64_kernel<<<296, 256>>>(3);
    proj64_kernel<<<NPTS/64, 256>>>(3, W4);
    pool_plain_kernel<<<NPTS*64/256, 256>>>(b4, 4);

    // ---- head ----
    starts_kernel<<<1, 32>>>(n_pts);
    agg_kernel<<<64, 256>>>();
    final_kernel<<<64, 128>>>(Wp, bp, out);
}

// round 10
// speedup vs baseline: 1.0645x; 1.0074x over previous
#include <cuda_runtime.h>
#include <math_constants.h>

#define NPTS 16384
#define KK 10
#define CB 64
#define PAD 68
#define BR 32
#define BC 64
#define NT (NPTS/BC)     /* 256 col tiles per sweep */
#define NCH (NPTS/BR)    /* 512 row chunks */

// ---------------- scratch (device globals; no allocation) ----------------
__device__ __align__(16) float d_sq[NPTS];
__device__ int   d_idx[NPTS*KK];
__device__ __align__(16) float d_f1[NPTS*CB];
__device__ __align__(16) float d_f2[NPTS*CB];
__device__ __align__(16) float d_f3[NPTS*CB];
__device__ __align__(16) float d_f4[NPTS*CB];
__device__ __align__(16) float d_Abuf[NPTS*CB];
__device__ __align__(16) float d_Cbuf[NPTS*CB];
__device__ __align__(16) float d_maxh[NPTS*CB];
__device__ __align__(16) float d_minh[NPTS*CB];
__device__ float d_sum[CB];
__device__ float d_ss[CB];
__device__ int   d_ctr;
__device__ int   d_starts[65];
__device__ float d_P[64*256];

// Resolve feature-buffer id -> device pointer IN DEVICE CODE (host-side
// __device__ symbol decay passes the host shadow address under ATS).
__device__ __forceinline__ float* fbuf(int id){
    switch(id){
        case 1: return d_f1;
        case 2: return d_f2;
        case 3: return d_f3;
        default: return d_f4;
    }
}

// ---------------- packed f32x2 helpers ----------------
__device__ __forceinline__ unsigned long long ffma2(unsigned long long a, unsigned long long b, unsigned long long c){
    unsigned long long r;
    asm("fma.rn.f32x2 %0, %1, %2, %3;" : "=l"(r) : "l"(a), "l"(b), "l"(c));
    return r;
}
__device__ __forceinline__ float hsum2(unsigned long long v){
    float lo, hi;
    asm("mov.b64 {%0,%1}, %2;" : "=f"(lo), "=f"(hi) : "l"(v));
    return lo + hi;
}

// ---------------- cp.async helpers ----------------
__device__ __forceinline__ unsigned smaddr(const void* p){
    return (unsigned)__cvta_generic_to_shared(p);
}
__device__ __forceinline__ void cp16(unsigned s, const void* g){
    asm volatile("cp.async.cg.shared.global [%0], [%1], 16;" :: "r"(s), "l"(g));
}
__device__ __forceinline__ void cp4(unsigned s, const void* g){
    asm volatile("cp.async.ca.shared.global [%0], [%1], 4;" :: "r"(s), "l"(g));
}
__device__ __forceinline__ void cp_commit(){ asm volatile("cp.async.commit_group;"); }
__device__ __forceinline__ void cp_wait1(){ asm volatile("cp.async.wait_group 1;"); }
__device__ __forceinline__ void cp_wait0(){ asm volatile("cp.async.wait_group 0;"); }

// ---------------- launch 1: fused kNN(3D) + projection(C=3) + stat reset ----
__global__ __launch_bounds__(128) void knn3proj3_kernel(const float* __restrict__ x,
                                                        const float* __restrict__ W){
    __shared__ float sWa[192], sWb[192];
    __shared__ float4 sc[256];
    const int t = threadIdx.x;
    const int i = blockIdx.x*128 + t;
    for (int v = t; v < 192; v += 128){
        float wb = W[192 + v];
        sWa[v] = W[v] - wb;
        sWb[v] = wb;
    }
    if (blockIdx.x == 0 && t < 64){ d_sum[t] = 0.f; d_ss[t] = 0.f; }
    float xi = x[i*3], yi = x[i*3+1], zi = x[i*3+2];
    float sqi = xi*xi + yi*yi + zi*zi;
    __syncthreads();

    // projection for this row: a = x@(Wt-Wb), c = x@Wb
    #pragma unroll 8
    for (int o = 0; o < 64; o++){
        float av = xi*sWa[o] + yi*sWa[64+o] + zi*sWa[128+o];
        float cv = xi*sWb[o] + yi*sWb[64+o] + zi*sWb[128+o];
        d_Abuf[i*64+o] = av; d_Cbuf[i*64+o] = cv;
    }

    // kNN over all 16384 candidates (norms computed inline)
    float bd[KK]; int bi[KK];
    #pragma unroll
    for (int q = 0; q < KK; q++){ bd[q] = CUDART_INF_F; bi[q] = 0x7fffffff; }
    for (int base = 0; base < NPTS; base += 256){
        __syncthreads();
        for (int v = t; v < 256; v += 128){
            int c = base + v;
            float xc = x[c*3], yc = x[c*3+1], zc = x[c*3+2];
            sc[v] = make_float4(xc, yc, zc, xc*xc + yc*yc + zc*zc);
        }
        __syncthreads();
        #pragma unroll 4
        for (int j = 0; j < 256; j++){
            float4 cv = sc[j];
            float dist = sqi + cv.w - 2.f*(xi*cv.x + yi*cv.y + zi*cv.z);
            if (dist < bd[KK-1]){
                float cd = dist; int ci = base + j;
                #pragma unroll
                for (int q = 0; q < KK; q++){
                    if (cd < bd[q]){ float td = bd[q]; int ti = bi[q]; bd[q] = cd; bi[q] = ci; cd = td; ci = ti; }
                }
            }
        }
    }
    #pragma unroll
    for (int q = 0; q < KK; q++) d_idx[i*KK+q] = bi[q];
}

// ---------------- kNN for 64-dim features: register-blocked distance GEMM ----
// Block = 256 threads = 32 row_pos x 8 col_pos. Thread: 1 row x 8 cols.
// Padded SMEM (stride 68 floats) => conflict-free. cp.async double buffer.
__global__ __launch_bounds__(256, 2) void knn64_kernel(int id){
    const float* f = fbuf(id);
    __shared__ union {
        struct { float srow[BR*PAD]; float scol[2][BC*PAD]; float ssq[2][BC]; } k;
        struct { float md[BR*8*KK]; int mi[BR*8*KK]; } m;
    } su;
    __shared__ int s_chunk;
    const int t = threadIdx.x;
    const int row_pos = t >> 3;   // 0..31
    const int col_pos = t & 7;    // 0..7
    const unsigned srow_u = smaddr(su.k.srow);
    const unsigned scol_u = smaddr(su.k.scol);
    const unsigned ssq_u  = smaddr(su.k.ssq);

    while (true){
        __syncthreads();
        if (t == 0) s_chunk = atomicAdd(&d_ctr, 1);
        __syncthreads();
        const int chunk = s_chunk;
        if (chunk >= NCH) return;            // uniform exit
        const int rbase = chunk*BR;

        // preload: row tile (32x64) + col tile 0 (64x64) + ssq tile 0
        #pragma unroll
        for (int i = 0; i < 2; i++){
            int v = t + i*256; int r = v >> 4, q = v & 15;
            cp16(srow_u + (unsigned)(r*PAD + q*4)*4u, f + (size_t)(rbase + r)*64 + q*4);
        }
        #pragma unroll
        for (int i = 0; i < 4; i++){
            int v = t + i*256; int c = v >> 4, q = v & 15;
            cp16(scol_u + (unsigned)(c*PAD + q*4)*4u, f + (size_t)c*64 + q*4);
        }
        if (t < BC) cp4(ssq_u + (unsigned)t*4u, d_sq + t);
        cp_commit();

        const float sqr = d_sq[rbase + row_pos];
        float bd[KK]; int bi[KK];
        #pragma unroll
        for (int q = 0; q < KK; q++){ bd[q] = CUDART_INF_F; bi[q] = 0x7fffffff; }

        for (int tile = 0; tile < NT; tile++){
            const int buf = tile & 1;
            if (tile + 1 < NT){
                const int nb = buf ^ 1;
                const int cb0 = (tile + 1)*BC;
                const unsigned sc_nb = scol_u + (unsigned)(nb*BC*PAD)*4u;
                #pragma unroll
                for (int i = 0; i < 4; i++){
                    int v = t + i*256; int c = v >> 4, q = v & 15;
                    cp16(sc_nb + (unsigned)(c*PAD + q*4)*4u, f + (size_t)(cb0 + c)*64 + q*4);
                }
                if (t < BC) cp4(ssq_u + (unsigned)(nb*BC + t)*4u, d_sq + cb0 + t);
                cp_commit();
                cp_wait1();
            } else {
                cp_wait0();
            }
            __syncthreads();

            // ---- GEMM micro-tile: 1 row x 8 cols over k=64 (16 k-quads) ----
            const float* cb = su.k.scol[buf];
            const float* rowp = su.k.srow + row_pos*PAD;
            unsigned long long acc[8];
            #pragma unroll
            for (int j = 0; j < 8; j++) acc[j] = 0ull;
            #pragma unroll
            for (int kq = 0; kq < 16; kq++){
                ulonglong2 rf = *(const ulonglong2*)(rowp + kq*4);
                #pragma unroll
                for (int j = 0; j < 8; j++){
                    ulonglong2 cf = *(const ulonglong2*)(cb + (col_pos + 8*j)*PAD + kq*4);
                    acc[j] = ffma2(rf.x, cf.x, acc[j]);
                    acc[j] = ffma2(rf.y, cf.y, acc[j]);
                }
            }
            // ---- epilogue: form distances, streaming top-10 insert ----
            #pragma unroll
            for (int j = 0; j < 8; j++){
                int cc = col_pos + 8*j;
                float dist = fmaf(-2.f, hsum2(acc[j]), sqr + su.k.ssq[buf][cc]);
                if (dist < bd[KK-1]){
                    float cd = dist; int ci = tile*BC + cc;
                    #pragma unroll
                    for (int q = 0; q < KK; q++){
                        if (cd < bd[q]){ float td = bd[q]; int ti = bi[q]; bd[q] = cd; bi[q] = ci; cd = td; ci = ti; }
                    }
                }
            }
            __syncthreads();   // protect buf^1 before next iteration's cp.async
        }

        // ---- merge the 8 per-thread lists per row (lexicographic (dist,idx)) ----
        #pragma unroll
        for (int q = 0; q < KK; q++){
            su.m.md[(row_pos*8 + col_pos)*KK + q] = bd[q];
            su.m.mi[(row_pos*8 + col_pos)*KK + q] = bi[q];
        }
        __syncthreads();
        if (t < BR){
            float fd[KK]; int fi[KK];
            #pragma unroll
            for (int q = 0; q < KK; q++){ fd[q] = CUDART_INF_F; fi[q] = 0x7fffffff; }
            for (int s = 0; s < 8*KK; s++){
                float dv = su.m.md[t*8*KK + s];
                int   iv = su.m.mi[t*8*KK + s];
                if (dv < fd[KK-1] || (dv == fd[KK-1] && iv < fi[KK-1])){
                    float cd = dv; int ci = iv;
                    #pragma unroll
                    for (int q = 0; q < KK; q++){
                        if (cd < fd[q] || (cd == fd[q] && ci < fi[q])){
                            float td = fd[q]; int ti = fi[q]; fd[q] = cd; fi[q] = ci; cd = td; ci = ti;
                        }
                    }
                }
            }
            #pragma unroll
            for (int q = 0; q < KK; q++) d_idx[(rbase + t)*KK + q] = fi[q];
        }
        // loop-top __syncthreads() orders merge writes vs next chunk's cp.async
    }
}

// ---------------- per-point projections (C=64): a = x@(Wt-Wb), c = x@Wb -----
__global__ void proj64_kernel(int id, const float* __restrict__ W){
    const float* x = fbuf(id);
    __shared__ float sWa[64*64];
    __shared__ float sWb[64*64];
    for (int v = threadIdx.x; v < 64*64; v += 256){
        float wb = W[64*64 + v];
        sWa[v] = W[v] - wb;
        sWb[v] = wb;
    }
    __syncthreads();
    int o  = threadIdx.x & 63;
    int rg = threadIdx.x >> 6;
    int row0 = blockIdx.x * 64;
    for (int rr = 0; rr < 64; rr += 4){
        int row = row0 + rr + rg;
        float av = 0.f, cv = 0.f;
        #pragma unroll
        for (int d = 0; d < 64; d++){
            float xv = __ldg(x + (long)row*64 + d);
            av += xv * sWa[d*64+o];
            cv += xv * sWb[d*64+o];
        }
        d_Abuf[row*64+o] = av; d_Cbuf[row*64+o] = cv;
    }
}

// ---------------- gather + pool (BN layers: stats + max/min) ----------------
__global__ void pool_bn_kernel(const float* __restrict__ bias){
    int o  = threadIdx.x & 63;
    int rg = threadIdx.x >> 6;
    int row = blockIdx.x*4 + rg;
    float a = d_Abuf[row*64+o] + bias[o];
    float mx = -CUDART_INF_F, mn = CUDART_INF_F, s = 0.f, s2 = 0.f;
    #pragma unroll
    for (int k = 0; k < KK; k++){
        int j = d_idx[row*KK+k];
        float h = a + d_Cbuf[j*64+o];
        mx = fmaxf(mx, h); mn = fminf(mn, h);
        s += h; s2 += h*h;
    }
    d_maxh[row*64+o] = mx; d_minh[row*64+o] = mn;
    __shared__ float reds[4][64], reds2[4][64];
    reds[rg][o] = s; reds2[rg][o] = s2;
    __syncthreads();
    if (rg == 0){
        float ts = reds[0][o]+reds[1][o]+reds[2][o]+reds[3][o];
        float t2 = reds2[0][o]+reds2[1][o]+reds2[2][o]+reds2[3][o];
        atomicAdd(&d_sum[o], ts);
        atomicAdd(&d_ss[o],  t2);
    }
}

// BN apply -> feature buffer, fused per-row squared-norm reduction + ctr reset
__global__ void bn_apply_sq_kernel(const float* __restrict__ gamma, const float* __restrict__ beta,
                                   int outid){
    float* out = fbuf(outid);
    int t = threadIdx.x;
    int gid = blockIdx.x*256 + t;
    int o = t & 63;
    const float inv = 1.f/(float)(NPTS*KK);
    float mu  = d_sum[o]*inv;
    float var = d_ss[o]*inv - mu*mu;
    float g = gamma[o];
    float s = rsqrtf(var + 1e-5f) * g;
    float pool = (g >= 0.f) ? d_maxh[gid] : d_minh[gid];
    float v = fmaxf(pool*s + (beta[o] - mu*s), 0.f);
    out[gid] = v;
    // per-row squared norm (4 rows per block, 2 warps per row)
    float w = v*v;
    #pragma unroll
    for (int off = 16; off > 0; off >>= 1) w += __shfl_xor_sync(0xffffffffu, w, off);
    __shared__ float part[8];
    if ((t & 31) == 0) part[t>>5] = w;
    __syncthreads();
    if (t < 4) d_sq[blockIdx.x*4 + t] = part[2*t] + part[2*t+1];
    if (blockIdx.x == 0 && t == 0) d_ctr = 0;
}

// plain pool -> feature buffer, fused per-row squared-norm + ctr/stat reset
__global__ void pool_plain_sq_kernel(const float* __restrict__ bias, int outid){
    float* out = fbuf(outid);
    int t = threadIdx.x;
    int gid = blockIdx.x*256 + t;
    int o = t & 63; int row = gid >> 6;
    float cmax = -CUDART_INF_F;
    #pragma unroll
    for (int k = 0; k < KK; k++){
        int j = d_idx[row*KK+k];
        cmax = fmaxf(cmax, d_Cbuf[j*64+o]);
    }
    float v = fmaxf(d_Abuf[gid] + bias[o] + cmax, 0.f);
    out[gid] = v;
    float w = v*v;
    #pragma unroll
    for (int off = 16; off > 0; off >>= 1) w += __shfl_xor_sync(0xffffffffu, w, off);
    __shared__ float part[8];
    if ((t & 31) == 0) part[t>>5] = w;
    __syncthreads();
    if (t < 4) d_sq[blockIdx.x*4 + t] = part[2*t] + part[2*t+1];
    if (blockIdx.x == 0 && t == 0) d_ctr = 0;
    if (blockIdx.x == 0 && t < 64){ d_sum[t] = 0.f; d_ss[t] = 0.f; }
}

// ---------------- head ----------------
__global__ void starts_kernel(const int* __restrict__ n_pts){
    if (threadIdx.x == 0){
        int acc = 0;
        for (int b = 0; b < 64; b++){ d_starts[b] = acc; acc += n_pts[b]; }
        d_starts[64] = acc;
    }
}

__global__ void agg_kernel(){
    int b = blockIdx.x;
    int l = threadIdx.x >> 6, o = threadIdx.x & 63;
    const float* f = (l == 0) ? d_f1 : (l == 1) ? d_f2 : (l == 2) ? d_f3 : d_f4;
    int s = min(d_starts[b], NPTS);
    int e = (b == 63) ? NPTS : min(d_starts[b+1], NPTS);
    float m = -CUDART_INF_F;
    for (int p = s; p < e; p++) m = fmaxf(m, f[p*64+o]);
    d_P[b*256 + l*64 + o] = m;
}

__global__ void final_kernel(const float* __restrict__ Wp, const float* __restrict__ bp,
                             float* __restrict__ out){
    int b = blockIdx.x; int o = threadIdx.x;  // 128 threads
    __shared__ float sp[256];
    for (int v = o; v < 256; v += 128) sp[v] = d_P[b*256+v];
    __syncthreads();
    float acc = bp[o];
    #pragma unroll 4
    for (int d = 0; d < 256; d++) acc += sp[d]*Wp[d*128+o];
    float v = tanhf(acc);
    float sq = v*v;
    #pragma unroll
    for (int off = 16; off > 0; off >>= 1) sq += __shfl_xor_sync(0xffffffffu, sq, off);
    __shared__ float rs[4];
    if ((o & 31) == 0) rs[o>>5] = sq;
    __syncthreads();
    float tot = rs[0]+rs[1]+rs[2]+rs[3];
    out[b*128+o] = v / (sqrtf(tot) + 1e-9f);
}

// ---------------- launch ----------------
extern "C" void kernel_launch(void* const* d_in, const int* in_sizes, int n_in,
                              void* d_out, int out_size){
    (void)in_sizes; (void)n_in; (void)out_size;
    const float* x     = (const float*)d_in[0];
    const int*   n_pts = (const int*)  d_in[1];
    const float* W1 = (const float*)d_in[2];  const float* b1  = (const float*)d_in[3];
    const float* g1 = (const float*)d_in[4];  const float* be1 = (const float*)d_in[5];
    const float* W2 = (const float*)d_in[6];  const float* b2  = (const float*)d_in[7];
    const float* W3 = (const float*)d_in[8];  const float* b3  = (const float*)d_in[9];
    const float* g3 = (const float*)d_in[10]; const float* be3 = (const float*)d_in[11];
    const float* W4 = (const float*)d_in[12]; const float* b4  = (const float*)d_in[13];
    const float* Wp = (const float*)d_in[14]; const float* bp  = (const float*)d_in[15];
    float* out = (float*)d_out;

    // ---- layer 1 (C=3, BN) ----  [3 launches]
    knn3proj3_kernel<<<128, 128>>>(x, W1);                 // #1 (+reset sums)
    pool_bn_kernel<<<NPTS/4, 256>>>(b1);                   // #2
    bn_apply_sq_kernel<<<NPTS/4, 256>>>(g1, be1, 1);       // #3 -> f1, sq(f1), ctr=0

    // ---- layer 2 (C=64, no BN) ----
    knn64_kernel<<<296, 256>>>(1);                         // #4  <- ncu capture
    proj64_kernel<<<NPTS/64, 256>>>(1, W2);                // #5
    pool_plain_sq_kernel<<<NPTS/4, 256>>>(b2, 2);          // #6 -> f2, sq(f2), ctr=0, sums=0

    // ---- layer 3 (C=64, BN) ----
    knn64_kernel<<<296, 256>>>(2);                         // #7
    proj64_kernel<<<NPTS/64, 256>>>(2, W3);                // #8
    pool_bn_kernel<<<NPTS/4, 256>>>(b3);                   // #9
    bn_apply_sq_kernel<<<NPTS/4, 256>>>(g3, be3, 3);       // #10 -> f3, sq(f3), ctr=0

    // ---- layer 4 (C=64, no BN) ----
    knn64_kernel<<<296, 256>>>(3);                         // #11
    proj64_kernel<<<NPTS/64, 256>>>(3, W4);                // #12
    pool_plain_sq_kernel<<<NPTS/4, 256>>>(b4, 4);          // #13 -> f4

    // ---- head ----
    starts_kernel<<<1, 32>>>(n_pts);                       // #14
    agg_kernel<<<64, 256>>>();                             // #15
    final_kernel<<<64, 128>>>(Wp, bp, out);                // #16
}

// round 11
// speedup vs baseline: 1.7631x; 1.6563x over previous
#include <cuda_runtime.h>
#include <math_constants.h>

#define NPTS 16384
#define KK 10
#define CB 64

// knn64 tiling
#define KBR 128                 /* rows per block */
#define KBC 128                 /* cols per tile */
#define KNT (NPTS/KBC)          /* 128 col tiles */
#define KNCH (NPTS/KBR)         /* 128 chunks = grid */

// dynamic smem layout for knn64 (bytes)
#define SM_SCOL   0             /* 2 x 32768 (swizzled col tiles) */
#define SM_SROW   65536         /* 32768 (swizzled row tile) */
#define SM_SDIST  98304         /* 128 x 132 floats = 67584 */
#define SM_SSQC   165888        /* 2 x 128 floats */
#define SM_SRQ    166912        /* 128 floats */
#define SMEM_K    167424

// ---------------- scratch (device globals; no allocation) ----------------
__device__ __align__(16) float d_sq[NPTS];
__device__ int   d_idx[NPTS*KK];
__device__ __align__(16) float d_f1[NPTS*CB];
__device__ __align__(16) float d_f2[NPTS*CB];
__device__ __align__(16) float d_f3[NPTS*CB];
__device__ __align__(16) float d_f4[NPTS*CB];
__device__ __align__(16) float d_Abuf[NPTS*CB];
__device__ __align__(16) float d_Cbuf[NPTS*CB];
__device__ __align__(16) float d_maxh[NPTS*CB];
__device__ __align__(16) float d_minh[NPTS*CB];
__device__ float d_sum[CB];
__device__ float d_ss[CB];
__device__ int   d_ctr;
__device__ int   d_starts[65];
__device__ float d_P[64*256];

// Resolve feature-buffer id -> device pointer IN DEVICE CODE (host-side
// __device__ symbol decay passes the host shadow address under ATS).
__device__ __forceinline__ float* fbuf(int id){
    switch(id){
        case 1: return d_f1;
        case 2: return d_f2;
        case 3: return d_f3;
        default: return d_f4;
    }
}

// ---------------- packed f32x2 helpers ----------------
__device__ __forceinline__ unsigned long long ffma2(unsigned long long a, unsigned long long b, unsigned long long c){
    unsigned long long r;
    asm("fma.rn.f32x2 %0, %1, %2, %3;" : "=l"(r) : "l"(a), "l"(b), "l"(c));
    return r;
}
__device__ __forceinline__ float hsum2(unsigned long long v){
    float lo, hi;
    asm("mov.b64 {%0,%1}, %2;" : "=f"(lo), "=f"(hi) : "l"(v));
    return lo + hi;
}

// ---------------- cp.async helpers ----------------
__device__ __forceinline__ unsigned smaddr(const void* p){
    return (unsigned)__cvta_generic_to_shared(p);
}
__device__ __forceinline__ void cp16(unsigned s, const void* g){
    asm volatile("cp.async.cg.shared.global [%0], [%1], 16;" :: "r"(s), "l"(g));
}
__device__ __forceinline__ void cp4(unsigned s, const void* g){
    asm volatile("cp.async.ca.shared.global [%0], [%1], 4;" :: "r"(s), "l"(g));
}
__device__ __forceinline__ void cp_commit(){ asm volatile("cp.async.commit_group;"); }
__device__ __forceinline__ void cp_wait1(){ asm volatile("cp.async.wait_group 1;"); }
__device__ __forceinline__ void cp_wait0(){ asm volatile("cp.async.wait_group 0;"); }

// ---------------- launch 1: fused kNN(3D) + projection(C=3) + stat reset ----
__global__ __launch_bounds__(128) void knn3proj3_kernel(const float* __restrict__ x,
                                                        const float* __restrict__ W){
    __shared__ float sWa[192], sWb[192];
    __shared__ float4 sc[256];
    const int t = threadIdx.x;
    const int i = blockIdx.x*128 + t;
    for (int v = t; v < 192; v += 128){
        float wb = W[192 + v];
        sWa[v] = W[v] - wb;
        sWb[v] = wb;
    }
    if (blockIdx.x == 0 && t < 64){ d_sum[t] = 0.f; d_ss[t] = 0.f; }
    float xi = x[i*3], yi = x[i*3+1], zi = x[i*3+2];
    float sqi = xi*xi + yi*yi + zi*zi;
    __syncthreads();

    #pragma unroll 8
    for (int o = 0; o < 64; o++){
        float av = xi*sWa[o] + yi*sWa[64+o] + zi*sWa[128+o];
        float cv = xi*sWb[o] + yi*sWb[64+o] + zi*sWb[128+o];
        d_Abuf[i*64+o] = av; d_Cbuf[i*64+o] = cv;
    }

    float bd[KK]; int bi[KK];
    #pragma unroll
    for (int q = 0; q < KK; q++){ bd[q] = CUDART_INF_F; bi[q] = 0x7fffffff; }
    for (int base = 0; base < NPTS; base += 256){
        __syncthreads();
        for (int v = t; v < 256; v += 128){
            int c = base + v;
            float xc = x[c*3], yc = x[c*3+1], zc = x[c*3+2];
            sc[v] = make_float4(xc, yc, zc, xc*xc + yc*yc + zc*zc);
        }
        __syncthreads();
        #pragma unroll 4
        for (int j = 0; j < 256; j++){
            float4 cv = sc[j];
            float dist = sqi + cv.w - 2.f*(xi*cv.x + yi*cv.y + zi*cv.z);
            if (dist < bd[KK-1]){
                float cd = dist; int ci = base + j;
                #pragma unroll
                for (int q = 0; q < KK; q++){
                    if (cd < bd[q]){ float td = bd[q]; int ti = bi[q]; bd[q] = cd; bi[q] = ci; cd = td; ci = ti; }
                }
            }
        }
    }
    #pragma unroll
    for (int q = 0; q < KK; q++) d_idx[i*KK+q] = bi[q];
}

// ---------------- kNN-64: 8x8 register-tiled distance GEMM -------------------
// 256 threads = 16 rg x 16 cg; thread tile 8 rows x 8 cols; block 128x128.
// Swizzled smem tiles (16B chunk ^ group) -> conflict-free LDS.128.
// Epilogue: dist tile -> smem; selection: 2 threads/row, register top-10.
__global__ __launch_bounds__(256, 1) void knn64_kernel(int id){
    const float* f = fbuf(id);
    extern __shared__ char sm[];
    float* scolf = (float*)(sm + SM_SCOL);
    float* srowf = (float*)(sm + SM_SROW);
    float* sdist = (float*)(sm + SM_SDIST);
    float* ssqc  = (float*)(sm + SM_SSQC);
    float* srq   = (float*)(sm + SM_SRQ);
    const unsigned scol_u = smaddr(scolf);
    const unsigned srow_u = smaddr(srowf);
    const int t  = threadIdx.x;
    const int rg = t >> 4;           // 0..15
    const int cg = t & 15;           // 0..15
    const int rbase = blockIdx.x * KBR;
    const int selrow = t >> 1, selhalf = t & 1;

    // initial loads: row tile (swizzled), col tile 0 (swizzled), norms
    #pragma unroll
    for (int i = 0; i < 8; i++){
        int v = t + i*256; int r = v >> 4, q = v & 15;
        cp16(srow_u + (unsigned)((r<<8) + ((q ^ (r>>3)) << 4)),
             f + (size_t)(rbase + r)*64 + q*4);
    }
    #pragma unroll
    for (int i = 0; i < 8; i++){
        int v = t + i*256; int c = v >> 4, kqp = v & 15;
        cp16(scol_u + (unsigned)((kqp<<11) + ((c>>3)<<7) + ((((c&7) ^ ((c>>3)&7)))<<4)),
             f + (size_t)c*64 + kqp*4);
    }
    if (t < 128){
        cp4(smaddr(ssqc) + (unsigned)t*4u, d_sq + t);
        cp4(smaddr(srq)  + (unsigned)t*4u, d_sq + rbase + t);
    }
    cp_commit();

    float bd[KK]; int bi[KK];
    #pragma unroll
    for (int q = 0; q < KK; q++){ bd[q] = CUDART_INF_F; bi[q] = 0x7fffffff; }

    for (int tile = 0; tile < KNT; tile++){
        const int buf = tile & 1;
        if (tile + 1 < KNT){
            const int nb = buf ^ 1;
            const int cb0 = (tile + 1)*KBC;
            const unsigned sc_nb = scol_u + (unsigned)nb*32768u;
            #pragma unroll
            for (int i = 0; i < 8; i++){
                int v = t + i*256; int c = v >> 4, kqp = v & 15;
                cp16(sc_nb + (unsigned)((kqp<<11) + ((c>>3)<<7) + ((((c&7) ^ ((c>>3)&7)))<<4)),
                     f + (size_t)(cb0 + c)*64 + kqp*4);
            }
            if (t < 128) cp4(smaddr(ssqc) + (unsigned)(nb*128 + t)*4u, d_sq + cb0 + t);
            cp_commit();
            cp_wait1();
        } else {
            cp_wait0();
        }
        __syncthreads();   // tile data ready; also orders prev selection reads vs epilogue writes

        // ---- GEMM: 8x8 micro-tile over k=64 (16 k-quads) ----
        const float* cbf = scolf + buf*8192;    // floats
        unsigned long long acc[64];
        #pragma unroll
        for (int z = 0; z < 64; z++) acc[z] = 0ull;
        #pragma unroll 4
        for (int kqp = 0; kqp < 16; kqp++){
            ulonglong2 rv[8], cv[8];
            #pragma unroll
            for (int i = 0; i < 8; i++)
                rv[i] = *(const ulonglong2*)(srowf + ((rg*8+i)<<6) + ((kqp ^ rg) << 2));
            #pragma unroll
            for (int j = 0; j < 8; j++)
                cv[j] = *(const ulonglong2*)(cbf + (kqp<<9) + (cg<<5) + ((j ^ (cg&7)) << 2));
            #pragma unroll
            for (int i = 0; i < 8; i++){
                #pragma unroll
                for (int j = 0; j < 8; j++){
                    acc[i*8+j] = ffma2(rv[i].x, cv[j].x, acc[i*8+j]);
                    acc[i*8+j] = ffma2(rv[i].y, cv[j].y, acc[i*8+j]);
                }
            }
        }

        // ---- epilogue: distances -> sdist ----
        float scv[8];
        #pragma unroll
        for (int j = 0; j < 8; j++) scv[j] = ssqc[buf*128 + cg*8 + j];
        #pragma unroll
        for (int i = 0; i < 8; i++){
            int r = rg*8 + i;
            float sr = srq[r];
            float dj[8];
            #pragma unroll
            for (int j = 0; j < 8; j++)
                dj[j] = fmaf(-2.f, hsum2(acc[i*8+j]), sr + scv[j]);
            float4* dst = (float4*)(sdist + r*132 + cg*8);
            dst[0] = make_float4(dj[0], dj[1], dj[2], dj[3]);
            dst[1] = make_float4(dj[4], dj[5], dj[6], dj[7]);
        }
        __syncthreads();

        // ---- selection: 2 threads per row, 64 cols each ----
        {
            const float4* sp = (const float4*)sdist + selrow*33 + selhalf*16;
            int gbase = tile*KBC + selhalf*64;
            #pragma unroll 4
            for (int c2 = 0; c2 < 16; c2++){
                float4 v = sp[c2];
                int gi = gbase + c2*4;
                float dv; int iv;
                #pragma unroll
                for (int e = 0; e < 4; e++){
                    dv = (e==0)?v.x:(e==1)?v.y:(e==2)?v.z:v.w; iv = gi + e;
                    if (dv < bd[KK-1]){
                        float cd = dv; int ci = iv;
                        #pragma unroll
                        for (int q = 0; q < KK; q++){
                            if (cd < bd[q]){ float td = bd[q]; int ti = bi[q]; bd[q] = cd; bi[q] = ci; cd = td; ci = ti; }
                        }
                    }
                }
            }
        }
        // next loop-top __syncthreads orders these reads vs next epilogue writes
    }

    // ---- final merge: 2 half-lists per row, lexicographic (dist, idx) ----
    __syncthreads();
    float* md = sdist;                       // reuse
    int*   mi = (int*)(sdist + 2560);
    #pragma unroll
    for (int q = 0; q < KK; q++){
        md[(selrow*2 + selhalf)*KK + q] = bd[q];
        mi[(selrow*2 + selhalf)*KK + q] = bi[q];
    }
    __syncthreads();
    if (t < 128){
        const float* da = md + (t*2)*KK; const int* ia = mi + (t*2)*KK;
        const float* db = md + (t*2+1)*KK; const int* ib = mi + (t*2+1)*KK;
        int pa = 0, pb = 0;
        #pragma unroll
        for (int q = 0; q < KK; q++){
            int par = min(pa, KK-1), pbr = min(pb, KK-1);
            float va = da[par]; int ja = ia[par];
            float vb = db[pbr]; int jb = ib[pbr];
            bool takeA;
            if (pb >= KK) takeA = true;
            else if (pa >= KK) takeA = false;
            else takeA = (va < vb) || (va == vb && ja < jb);
            d_idx[(rbase + t)*KK + q] = takeA ? ja : jb;
            if (takeA) pa++; else pb++;
        }
    }
}

// ---------------- per-point projections (C=64): a = x@(Wt-Wb), c = x@Wb -----
__global__ void proj64_kernel(int id, const float* __restrict__ W){
    const float* x = fbuf(id);
    __shared__ float sWa[64*64];
    __shared__ float sWb[64*64];
    for (int v = threadIdx.x; v < 64*64; v += 256){
        float wb = W[64*64 + v];
        sWa[v] = W[v] - wb;
        sWb[v] = wb;
    }
    __syncthreads();
    int o  = threadIdx.x & 63;
    int rg = threadIdx.x >> 6;
    int row0 = blockIdx.x * 64;
    for (int rr = 0; rr < 64; rr += 4){
        int row = row0 + rr + rg;
        float av = 0.f, cv = 0.f;
        #pragma unroll
        for (int d = 0; d < 64; d++){
            float xv = __ldg(x + (long)row*64 + d);
            av += xv * sWa[d*64+o];
            cv += xv * sWb[d*64+o];
        }
        d_Abuf[row*64+o] = av; d_Cbuf[row*64+o] = cv;
    }
}

// ---------------- gather + pool (BN layers: stats + max/min) ----------------
__global__ void pool_bn_kernel(const float* __restrict__ bias){
    int o  = threadIdx.x & 63;
    int rg = threadIdx.x >> 6;
    int row = blockIdx.x*4 + rg;
    float a = d_Abuf[row*64+o] + bias[o];
    float mx = -CUDART_INF_F, mn = CUDART_INF_F, s = 0.f, s2 = 0.f;
    #pragma unroll
    for (int k = 0; k < KK; k++){
        int j = d_idx[row*KK+k];
        float h = a + d_Cbuf[j*64+o];
        mx = fmaxf(mx, h); mn = fminf(mn, h);
        s += h; s2 += h*h;
    }
    d_maxh[row*64+o] = mx; d_minh[row*64+o] = mn;
    __shared__ float reds[4][64], reds2[4][64];
    reds[rg][o] = s; reds2[rg][o] = s2;
    __syncthreads();
    if (rg == 0){
        float ts = reds[0][o]+reds[1][o]+reds[2][o]+reds[3][o];
        float t2 = reds2[0][o]+reds2[1][o]+reds2[2][o]+reds2[3][o];
        atomicAdd(&d_sum[o], ts);
        atomicAdd(&d_ss[o],  t2);
    }
}

// BN apply -> feature buffer, fused per-row squared-norm reduction
__global__ void bn_apply_sq_kernel(const float* __restrict__ gamma, const float* __restrict__ beta,
                                   int outid){
    float* out = fbuf(outid);
    int t = threadIdx.x;
    int gid = blockIdx.x*256 + t;
    int o = t & 63;
    const float inv = 1.f/(float)(NPTS*KK);
    float mu  = d_sum[o]*inv;
    float var = d_ss[o]*inv - mu*mu;
    float g = gamma[o];
    float s = rsqrtf(var + 1e-5f) * g;
    float pool = (g >= 0.f) ? d_maxh[gid] : d_minh[gid];
    float v = fmaxf(pool*s + (beta[o] - mu*s), 0.f);
    out[gid] = v;
    float w = v*v;
    #pragma unroll
    for (int off = 16; off > 0; off >>= 1) w += __shfl_xor_sync(0xffffffffu, w, off);
    __shared__ float part[8];
    if ((t & 31) == 0) part[t>>5] = w;
    __syncthreads();
    if (t < 4) d_sq[blockIdx.x*4 + t] = part[2*t] + part[2*t+1];
}

// plain pool -> feature buffer, fused per-row squared-norm + stat reset
__global__ void pool_plain_sq_kernel(const float* __restrict__ bias, int outid){
    float* out = fbuf(outid);
    int t = threadIdx.x;
    int gid = blockIdx.x*256 + t;
    int o = t & 63; int row = gid >> 6;
    float cmax = -CUDART_INF_F;
    #pragma unroll
    for (int k = 0; k < KK; k++){
        int j = d_idx[row*KK+k];
        cmax = fmaxf(cmax, d_Cbuf[j*64+o]);
    }
    float v = fmaxf(d_Abuf[gid] + bias[o] + cmax, 0.f);
    out[gid] = v;
    float w = v*v;
    #pragma unroll
    for (int off = 16; off > 0; off >>= 1) w += __shfl_xor_sync(0xffffffffu, w, off);
    __shared__ float part[8];
    if ((t & 31) == 0) part[t>>5] = w;
    __syncthreads();
    if (t < 4) d_sq[blockIdx.x*4 + t] = part[2*t] + part[2*t+1];
    if (blockIdx.x == 0 && t < 64){ d_sum[t] = 0.f; d_ss[t] = 0.f; }
}

// ---------------- head ----------------
__global__ void starts_kernel(const int* __restrict__ n_pts){
    if (threadIdx.x == 0){
        int acc = 0;
        for (int b = 0; b < 64; b++){ d_starts[b] = acc; acc += n_pts[b]; }
        d_starts[64] = acc;
    }
}

__global__ void agg_kernel(){
    int b = blockIdx.x;
    int l = threadIdx.x >> 6, o = threadIdx.x & 63;
    const float* f = (l == 0) ? d_f1 : (l == 1) ? d_f2 : (l == 2) ? d_f3 : d_f4;
    int s = min(d_starts[b], NPTS);
    int e = (b == 63) ? NPTS : min(d_starts[b+1], NPTS);
    float m = -CUDART_INF_F;
    for (int p = s; p < e; p++) m = fmaxf(m, f[p*64+o]);
    d_P[b*256 + l*64 + o] = m;
}

__global__ void final_kernel(const float* __restrict__ Wp, const float* __restrict__ bp,
                             float* __restrict__ out){
    int b = blockIdx.x; int o = threadIdx.x;  // 128 threads
    __shared__ float sp[256];
    for (int v = o; v < 256; v += 128) sp[v] = d_P[b*256+v];
    __syncthreads();
    float acc = bp[o];
    #pragma unroll 4
    for (int d = 0; d < 256; d++) acc += sp[d]*Wp[d*128+o];
    float v = tanhf(acc);
    float sq = v*v;
    #pragma unroll
    for (int off = 16; off > 0; off >>= 1) sq += __shfl_xor_sync(0xffffffffu, sq, off);
    __shared__ float rs[4];
    if ((o & 31) == 0) rs[o>>5] = sq;
    __syncthreads();
    float tot = rs[0]+rs[1]+rs[2]+rs[3];
    out[b*128+o] = v / (sqrtf(tot) + 1e-9f);
}

// ---------------- launch ----------------
extern "C" void kernel_launch(void* const* d_in, const int* in_sizes, int n_in,
                              void* d_out, int out_size){
    (void)in_sizes; (void)n_in; (void)out_size;
    const float* x     = (const float*)d_in[0];
    const int*   n_pts = (const int*)  d_in[1];
    const float* W1 = (const float*)d_in[2];  const float* b1  = (const float*)d_in[3];
    const float* g1 = (const float*)d_in[4];  const float* be1 = (const float*)d_in[5];
    const float* W2 = (const float*)d_in[6];  const float* b2  = (const float*)d_in[7];
    const float* W3 = (const float*)d_in[8];  const float* b3  = (const float*)d_in[9];
    const float* g3 = (const float*)d_in[10]; const float* be3 = (const float*)d_in[11];
    const float* W4 = (const float*)d_in[12]; const float* b4  = (const float*)d_in[13];
    const float* Wp = (const float*)d_in[14]; const float* bp  = (const float*)d_in[15];
    float* out = (float*)d_out;

    cudaFuncSetAttribute(knn64_kernel, cudaFuncAttributeMaxDynamicSharedMemorySize, SMEM_K);

    // ---- layer 1 (C=3, BN) ----
    knn3proj3_kernel<<<128, 128>>>(x, W1);                 // #1 (+reset sums)
    pool_bn_kernel<<<NPTS/4, 256>>>(b1);                   // #2
    bn_apply_sq_kernel<<<NPTS/4, 256>>>(g1, be1, 1);       // #3 -> f1, sq(f1)

    // ---- layer 2 (C=64, no BN) ----
    knn64_kernel<<<KNCH, 256, SMEM_K>>>(1);                // #4  <- ncu capture
    proj64_kernel<<<NPTS/64, 256>>>(1, W2);                // #5
    pool_plain_sq_kernel<<<NPTS/4, 256>>>(b2, 2);          // #6 -> f2, sq(f2), sums=0

    // ---- layer 3 (C=64, BN) ----
    knn64_kernel<<<KNCH, 256, SMEM_K>>>(2);                // #7
    proj64_kernel<<<NPTS/64, 256>>>(2, W3);                // #8
    pool_bn_kernel<<<NPTS/4, 256>>>(b3);                   // #9
    bn_apply_sq_kernel<<<NPTS/4, 256>>>(g3, be3, 3);       // #10 -> f3, sq(f3)

    // ---- layer 4 (C=64, no BN) ----
    knn64_kernel<<<KNCH, 256, SMEM_K>>>(3);                // #11
    proj64_kernel<<<NPTS/64, 256>>>(3, W4);                // #12
    pool_plain_sq_kernel<<<NPTS/4, 256>>>(b4, 4);          // #13 -> f4

    // ---- head ----
    starts_kernel<<<1, 32>>>(n_pts);                       // #14
    agg_kernel<<<64, 256>>>();                             // #15
    final_kernel<<<64, 128>>>(Wp, bp, out);                // #16
}